// round 5
// baseline (speedup 1.0000x reference)
#include <cuda_runtime.h>

// Problem constants
#define CN0 2048
#define CN1 8192
#define CN2 4096

// ---------------------------------------------------------------------------
// Scratch (device globals — no allocation allowed)
// ---------------------------------------------------------------------------
__device__ float g_X0cat[CN0 * 256];   // [x0 | x0p]
__device__ float g_T10[CN0 * 256];     // l0 @ X0cat
__device__ float g_T20[CN0 * 256];     // 2 l0 T10 - X0cat
__device__ float g_X1cat[CN1 * 256];   // [x1 | x1p]
__device__ float g_T1l[CN1 * 128];     // l1l @ x1
__device__ float g_T2l[CN1 * 128];
__device__ float g_T1u[CN1 * 256];     // l1u @ X1cat
__device__ float g_T2u[CN1 * 256];
__device__ float g_X2cat[CN2 * 256];   // [x2n | x2]
__device__ float g_T12[CN2 * 256];     // l2 @ X2cat
__device__ float g_T22[CN2 * 256];
__device__ float g_W0[6 * 16384];      // repacked w0: [c][i][o]
__device__ float g_W1[8 * 16384];
__device__ float g_W2[6 * 16384];

// ---------------------------------------------------------------------------
// Packed f32x2 helpers (Blackwell FFMA2 path)
// ---------------------------------------------------------------------------
__device__ __forceinline__ unsigned long long dup2(float a) {
    unsigned long long r;
    unsigned u = __float_as_uint(a);
    asm("mov.b64 %0, {%1, %1};" : "=l"(r) : "r"(u));
    return r;
}
__device__ __forceinline__ void fma2(unsigned long long& d,
                                     unsigned long long a,
                                     unsigned long long b) {
    asm("fma.rn.f32x2 %0, %1, %2, %0;" : "+l"(d) : "l"(a), "l"(b));
}
__device__ __forceinline__ float2 un2(unsigned long long v) {
    unsigned lo, hi;
    asm("mov.b64 {%0, %1}, %2;" : "=r"(lo), "=r"(hi) : "l"(v));
    return make_float2(__uint_as_float(lo), __uint_as_float(hi));
}

// ---------------------------------------------------------------------------
// Tile loaders (128-wide M/N tile, 16-deep K tile, 256 threads)
// ---------------------------------------------------------------------------
__device__ __forceinline__ void ldA_n(float (*As)[132], const float* __restrict__ A,
                                      int lda, int m0, int k0, int tid) {
#pragma unroll
    for (int l = 0; l < 2; l++) {
        int idx = tid + l * 256;
        int row = idx >> 2;              // 0..127
        int kq  = (idx & 3) << 2;        // 0,4,8,12
        float4 v = *(const float4*)(A + (size_t)(m0 + row) * lda + k0 + kq);
        As[kq + 0][row] = v.x;
        As[kq + 1][row] = v.y;
        As[kq + 2][row] = v.z;
        As[kq + 3][row] = v.w;
    }
}
__device__ __forceinline__ void ldA_t(float (*As)[132], const float* __restrict__ A,
                                      int lda, int m0, int k0, int tid) {
#pragma unroll
    for (int l = 0; l < 2; l++) {
        int idx = tid + l * 256;
        int kr = idx >> 5;               // 0..15
        int mq = (idx & 31) << 2;        // 0..124
        *(float4*)(&As[kr][mq]) =
            *(const float4*)(A + (size_t)(k0 + kr) * lda + m0 + mq);
    }
}
__device__ __forceinline__ void ldB(float (*Bs)[128], const float* __restrict__ B,
                                    int ldb, int n0, int k0,
                                    const float* __restrict__ bscale, int bss, int tid) {
#pragma unroll
    for (int l = 0; l < 2; l++) {
        int idx = tid + l * 256;
        int kr = idx >> 5;
        int nq = (idx & 31) << 2;
        float4 v = *(const float4*)(B + (size_t)(k0 + kr) * ldb + n0 + nq);
        if (bscale) {
            float s = bscale[(size_t)(k0 + kr) * bss];
            v.x *= s; v.y *= s; v.z *= s; v.w *= s;
        }
        *(float4*)(&Bs[kr][nq]) = v;
    }
}

// Inner product over one 16-deep K tile. acc[i][j] holds column pairs:
//   j=0: cols tx*4+{0,1}; j=1: tx*4+{2,3}; j=2: 64+tx*4+{0,1}; j=3: 64+tx*4+{2,3}
// rows: m0 + ty*8 + i.
__device__ __forceinline__ void mm_inner(float (*As)[132], float (*Bs)[128],
                                         int tx, int ty,
                                         unsigned long long acc[8][4]) {
#pragma unroll
    for (int kk = 0; kk < 16; kk++) {
        float4 a0 = *(const float4*)(&As[kk][ty * 8]);
        float4 a1 = *(const float4*)(&As[kk][ty * 8 + 4]);
        double2 bA = *(const double2*)(&Bs[kk][tx * 4]);
        double2 bB = *(const double2*)(&Bs[kk][64 + tx * 4]);
        unsigned long long bp[4];
        bp[0] = __double_as_longlong(bA.x);
        bp[1] = __double_as_longlong(bA.y);
        bp[2] = __double_as_longlong(bB.x);
        bp[3] = __double_as_longlong(bB.y);
        float av[8] = {a0.x, a0.y, a0.z, a0.w, a1.x, a1.y, a1.z, a1.w};
#pragma unroll
        for (int i = 0; i < 8; i++) {
            unsigned long long ap = dup2(av[i]);
#pragma unroll
            for (int j = 0; j < 4; j++) fma2(acc[i][j], ap, bp[j]);
        }
    }
}

// ---------------------------------------------------------------------------
// Batched GEMM: several independent GEMMs in one launch (fills the chip)
// ---------------------------------------------------------------------------
struct GemmDesc {
    const float* A;
    const float* B;
    const float* S;       // subtrahend for Chebyshev epilogue (epi=1)
    const float* bscale;  // diag matrix base for B row scaling (or null)
    const float* crow;    // diag matrix base for C row scaling (or null)
    float* C;
    int lda, ldb, lds, ldc;
    int bss, crs;         // diag strides (N+1)
    int K, mtiles, ntiles, tile_base;
    int transa, epi;      // epi: 0 = store (opt. row-scaled), 1 = 2*AB - S
};
struct BatchArgs { GemmDesc d[4]; int nd; };

__global__ __launch_bounds__(256, 2) void gemm_batched(BatchArgs args) {
    __shared__ __align__(16) float As[16][132];
    __shared__ __align__(16) float Bs[16][128];
    int tid = threadIdx.x;
    int tx = tid & 15, ty = tid >> 4;
    int bid = blockIdx.x;

    int di = 0;
#pragma unroll
    for (int i = 1; i < 4; i++)
        if (i < args.nd && bid >= args.d[i].tile_base) di = i;
    const GemmDesc& g = args.d[di];

    int tile = bid - g.tile_base;
    int bm = tile / g.ntiles;
    int bn = tile - bm * g.ntiles;
    int m0 = bm << 7, n0 = bn << 7;

    unsigned long long acc[8][4];
#pragma unroll
    for (int i = 0; i < 8; i++)
#pragma unroll
        for (int j = 0; j < 4; j++) acc[i][j] = 0ull;

    const float* A = g.A;
    const float* B = g.B;
    const float* bscale = g.bscale;
    int lda = g.lda, ldb = g.ldb, K = g.K, transa = g.transa, bss = g.bss;

#pragma unroll 1
    for (int k0 = 0; k0 < K; k0 += 16) {
        if (transa) ldA_t(As, A, lda, m0, k0, tid);
        else        ldA_n(As, A, lda, m0, k0, tid);
        ldB(Bs, B, ldb, n0, k0, bscale, bss, tid);
        __syncthreads();
        mm_inner(As, Bs, tx, ty, acc);
        __syncthreads();
    }

    float* C = g.C;
    int ldc = g.ldc;
    if (g.epi == 0) {
        const float* crow = g.crow;
        int crs = g.crs;
#pragma unroll
        for (int i = 0; i < 8; i++) {
            int mr = m0 + ty * 8 + i;
            float s = crow ? crow[(size_t)mr * crs] : 1.0f;
#pragma unroll
            for (int gi = 0; gi < 2; gi++) {
                float2 lo = un2(acc[i][2 * gi]);
                float2 hi = un2(acc[i][2 * gi + 1]);
                float4 v = make_float4(lo.x * s, lo.y * s, hi.x * s, hi.y * s);
                *(float4*)(C + (size_t)mr * ldc + n0 + gi * 64 + tx * 4) = v;
            }
        }
    } else {
        const float* S = g.S;
        int lds = g.lds;
#pragma unroll
        for (int i = 0; i < 8; i++) {
            int mr = m0 + ty * 8 + i;
#pragma unroll
            for (int gi = 0; gi < 2; gi++) {
                int col = n0 + gi * 64 + tx * 4;
                float4 sv = *(const float4*)(S + (size_t)mr * lds + col);
                float2 lo = un2(acc[i][2 * gi]);
                float2 hi = un2(acc[i][2 * gi + 1]);
                float4 v = make_float4(2.0f * lo.x - sv.x, 2.0f * lo.y - sv.y,
                                       2.0f * hi.x - sv.z, 2.0f * hi.y - sv.w);
                *(float4*)(C + (size_t)mr * ldc + col) = v;
            }
        }
    }
}

// ---------------------------------------------------------------------------
// Combine: y = relu(sum_c A_c @ W_c), one CTA per 128-row tile, loops channels
// ---------------------------------------------------------------------------
__global__ __launch_bounds__(256, 2) void combine_kernel(float* __restrict__ out) {
    __shared__ __align__(16) float As[16][132];
    __shared__ __align__(16) float Bs[16][128];
    int tid = threadIdx.x;
    int tx = tid & 15, ty = tid >> 4;
    int bid = blockIdx.x;

    const float* chp[8];
    int chl[8];
    const float* W;
    float* op;
    int nc, bm;
    if (bid < 16) {                 // order 0: rows 2048
        bm = bid; nc = 6; W = g_W0; op = out;
        chp[0] = g_X0cat;        chl[0] = 256;
        chp[1] = g_T10;          chl[1] = 256;
        chp[2] = g_T20;          chl[2] = 256;
        chp[3] = g_X0cat + 128;  chl[3] = 256;
        chp[4] = g_T10 + 128;    chl[4] = 256;
        chp[5] = g_T20 + 128;    chl[5] = 256;
    } else if (bid < 80) {          // order 1: rows 8192
        bm = bid - 16; nc = 8; W = g_W1; op = out + (size_t)CN0 * 128;
        chp[0] = g_X1cat;        chl[0] = 256;
        chp[1] = g_T1l;          chl[1] = 128;
        chp[2] = g_T2l;          chl[2] = 128;
        chp[3] = g_T1u;          chl[3] = 256;
        chp[4] = g_T2u;          chl[4] = 256;
        chp[5] = g_X1cat + 128;  chl[5] = 256;
        chp[6] = g_T1u + 128;    chl[6] = 256;
        chp[7] = g_T2u + 128;    chl[7] = 256;
    } else {                        // order 2: rows 4096
        bm = bid - 80; nc = 6; W = g_W2; op = out + (size_t)(CN0 + CN1) * 128;
        chp[0] = g_X2cat;        chl[0] = 256;
        chp[1] = g_T12;          chl[1] = 256;
        chp[2] = g_T22;          chl[2] = 256;
        chp[3] = g_X2cat + 128;  chl[3] = 256;
        chp[4] = g_T12 + 128;    chl[4] = 256;
        chp[5] = g_T22 + 128;    chl[5] = 256;
    }
    int m0 = bm << 7;

    unsigned long long acc[8][4];
#pragma unroll
    for (int i = 0; i < 8; i++)
#pragma unroll
        for (int j = 0; j < 4; j++) acc[i][j] = 0ull;

#pragma unroll 1
    for (int c = 0; c < nc; c++) {
        const float* A = chp[c];
        int lda = chl[c];
        const float* Bw = W + c * 16384;
#pragma unroll 1
        for (int k0 = 0; k0 < 128; k0 += 16) {
            ldA_n(As, A, lda, m0, k0, tid);
            ldB(Bs, Bw, 128, 0, k0, nullptr, 0, tid);
            __syncthreads();
            mm_inner(As, Bs, tx, ty, acc);
            __syncthreads();
        }
    }

#pragma unroll
    for (int i = 0; i < 8; i++) {
        int mr = m0 + ty * 8 + i;
#pragma unroll
        for (int gi = 0; gi < 2; gi++) {
            float2 lo = un2(acc[i][2 * gi]);
            float2 hi = un2(acc[i][2 * gi + 1]);
            float4 v = make_float4(fmaxf(lo.x, 0.0f), fmaxf(lo.y, 0.0f),
                                   fmaxf(hi.x, 0.0f), fmaxf(hi.y, 0.0f));
            *(float4*)(op + (size_t)mr * 128 + gi * 64 + tx * 4) = v;
        }
    }
}

// ---------------------------------------------------------------------------
// Prep kernels
// ---------------------------------------------------------------------------
// Repack w[i][o][c] (k innermost) -> W[c][i][o]
__global__ void pack_kernel(float* __restrict__ dst, const float* __restrict__ w, int nk) {
    int idx = blockIdx.x * 256 + threadIdx.x;   // over 128*128 (i,o) pairs
    if (idx < 16384) {
        for (int c = 0; c < nk; c++) dst[c * 16384 + idx] = w[idx * nk + c];
    }
}
// Copy [rows,128] (ld 128) -> dst (ld 256)
__global__ void copy_kernel(float* __restrict__ dst, const float* __restrict__ src, int rows) {
    int idx = blockIdx.x * 256 + threadIdx.x;
    int r = idx >> 5, q = (idx & 31) << 2;
    if (r < rows)
        *(float4*)(dst + (size_t)r * 256 + q) = *(const float4*)(src + (size_t)r * 128 + q);
}

// ---------------------------------------------------------------------------
// Host launcher
// ---------------------------------------------------------------------------
static GemmDesc mk(const float* A, int lda, int ta,
                   const float* B, int ldb, const float* bs, int bss,
                   float* C, int ldc,
                   const float* cr, int crs,
                   const float* S, int lds,
                   int K, int mt, int nt, int base, int epi) {
    GemmDesc g;
    g.A = A; g.lda = lda; g.transa = ta;
    g.B = B; g.ldb = ldb; g.bscale = bs; g.bss = bss;
    g.C = C; g.ldc = ldc;
    g.crow = cr; g.crs = crs;
    g.S = S; g.lds = lds;
    g.K = K; g.mtiles = mt; g.ntiles = nt; g.tile_base = base; g.epi = epi;
    return g;
}

extern "C" void kernel_launch(void* const* d_in, const int* in_sizes, int n_in,
                              void* d_out, int out_size) {
    const float* x0  = (const float*)d_in[0];
    const float* x1  = (const float*)d_in[1];
    const float* x2  = (const float*)d_in[2];
    const float* b1  = (const float*)d_in[3];
    const float* b2  = (const float*)d_in[4];
    const float* l0  = (const float*)d_in[5];
    const float* l1l = (const float*)d_in[6];
    const float* l1u = (const float*)d_in[7];
    const float* l2  = (const float*)d_in[8];
    const float* d1  = (const float*)d_in[9];    // diag matrix [N0,N0]
    const float* d3  = (const float*)d_in[10];   // diag matrix [N2,N2]
    const float* d5  = (const float*)d_in[11];   // diag matrix [N1,N1]
    const float* w0  = (const float*)d_in[12];
    const float* w1  = (const float*)d_in[13];
    const float* w2  = (const float*)d_in[14];
    float* out = (float*)d_out;
    (void)in_sizes; (void)n_in; (void)out_size;

    float *X0cat, *T10, *T20, *X1cat, *T1l, *T2l, *T1u, *T2u, *X2cat, *T12, *T22;
    float *W0, *W1, *W2;
    cudaGetSymbolAddress((void**)&X0cat, g_X0cat);
    cudaGetSymbolAddress((void**)&T10,   g_T10);
    cudaGetSymbolAddress((void**)&T20,   g_T20);
    cudaGetSymbolAddress((void**)&X1cat, g_X1cat);
    cudaGetSymbolAddress((void**)&T1l,   g_T1l);
    cudaGetSymbolAddress((void**)&T2l,   g_T2l);
    cudaGetSymbolAddress((void**)&T1u,   g_T1u);
    cudaGetSymbolAddress((void**)&T2u,   g_T2u);
    cudaGetSymbolAddress((void**)&X2cat, g_X2cat);
    cudaGetSymbolAddress((void**)&T12,   g_T12);
    cudaGetSymbolAddress((void**)&T22,   g_T22);
    cudaGetSymbolAddress((void**)&W0,    g_W0);
    cudaGetSymbolAddress((void**)&W1,    g_W1);
    cudaGetSymbolAddress((void**)&W2,    g_W2);

    // Prep: weight repack + feature copies into concatenated panels
    pack_kernel<<<64, 256>>>(W0, w0, 6);
    pack_kernel<<<64, 256>>>(W1, w1, 8);
    pack_kernel<<<64, 256>>>(W2, w2, 6);
    copy_kernel<<<CN0 * 32 / 256, 256>>>(X0cat,       x0, CN0);  // X0cat[:, :128] = x0
    copy_kernel<<<CN1 * 32 / 256, 256>>>(X1cat,       x1, CN1);  // X1cat[:, :128] = x1
    copy_kernel<<<CN2 * 32 / 256, 256>>>(X2cat + 128, x2, CN2);  // X2cat[:,128:]  = x2

    // Wave 1: projections (all independent) — 112 CTAs
    BatchArgs ba; ba.nd = 3;
    // x0p = d1_inv * (b1 @ x1) -> X0cat[:,128:]
    ba.d[0] = mk(b1, CN1, 0, x1, 128, nullptr, 0, X0cat + 128, 256,
                 d1, CN0 + 1, nullptr, 0, CN1, 16, 1, 0, 0);
    // x1p = b2 @ (d3 * x2) -> X1cat[:,128:]
    ba.d[1] = mk(b2, CN2, 0, x2, 128, d3, CN2 + 1, X1cat + 128, 256,
                 nullptr, 0, nullptr, 0, CN2, 64, 1, 16, 0);
    // x2n = b2^T @ (d5_pinv * x1) -> X2cat[:,:128]
    ba.d[2] = mk(b2, CN2, 1, x1, 128, d5, CN1 + 1, X2cat, 256,
                 nullptr, 0, nullptr, 0, CN1, 32, 1, 80, 0);
    gemm_batched<<<112, 256>>>(ba);

    // Wave 2: first Chebyshev terms T1 = L @ X — 288 CTAs
    BatchArgs bb; bb.nd = 4;
    bb.d[0] = mk(l0,  CN0, 0, X0cat, 256, nullptr, 0, T10, 256,
                 nullptr, 0, nullptr, 0, CN0, 16, 2, 0, 0);
    bb.d[1] = mk(l1l, CN1, 0, x1,    128, nullptr, 0, T1l, 128,
                 nullptr, 0, nullptr, 0, CN1, 64, 1, 32, 0);
    bb.d[2] = mk(l1u, CN1, 0, X1cat, 256, nullptr, 0, T1u, 256,
                 nullptr, 0, nullptr, 0, CN1, 64, 2, 96, 0);
    bb.d[3] = mk(l2,  CN2, 0, X2cat, 256, nullptr, 0, T12, 256,
                 nullptr, 0, nullptr, 0, CN2, 32, 2, 224, 0);
    gemm_batched<<<288, 256>>>(bb);

    // Wave 3: second Chebyshev terms T2 = 2 L T1 - X — 288 CTAs
    BatchArgs bc; bc.nd = 4;
    bc.d[0] = mk(l0,  CN0, 0, T10, 256, nullptr, 0, T20, 256,
                 nullptr, 0, X0cat, 256, CN0, 16, 2, 0, 1);
    bc.d[1] = mk(l1l, CN1, 0, T1l, 128, nullptr, 0, T2l, 128,
                 nullptr, 0, x1, 128, CN1, 64, 1, 32, 1);
    bc.d[2] = mk(l1u, CN1, 0, T1u, 256, nullptr, 0, T2u, 256,
                 nullptr, 0, X1cat, 256, CN1, 64, 2, 96, 1);
    bc.d[3] = mk(l2,  CN2, 0, T12, 256, nullptr, 0, T22, 256,
                 nullptr, 0, X2cat, 256, CN2, 32, 2, 224, 1);
    gemm_batched<<<288, 256>>>(bc);

    // Wave 4: channel combine + relu — 112 CTAs
    combine_kernel<<<112, 256>>>(out);
}